// round 7
// baseline (speedup 1.0000x reference)
#include <cuda_runtime.h>
#include <cuda_bf16.h>
#include <math.h>

// Problem constants (fixed by the reference)
#define NUM_NODES   100000
#define NUM_EDGES   1600000
#define EMBED_DIM   128
#define NUM_CLASSES 2
#define NUM_LAYERS  3

#define EDGES_PER_THREAD 8

// Scratch: __device__ globals (no allocations allowed).
__device__ float2 d_y [NUM_NODES];   // y = emb[idx] @ W
__device__ float2 d_p1[NUM_NODES];   // A y
__device__ float2 d_p2[NUM_NODES];   // A^2 y
__device__ float2 d_p3[NUM_NODES];   // A^3 y
__device__ float  d_a[NUM_LAYERS + 1]; // softmax(alpha)

// One 64-bit vector reduction per edge (no return -> REDG fast path in L2).
__device__ __forceinline__ void red_add_f2(float2* addr, float vx, float vy) {
    asm volatile("red.global.add.v2.f32 [%0], {%1, %2};"
                 :: "l"(addr), "f"(vx), "f"(vy) : "memory");
}

// 256-bit edge-stream load pinned in L2 (evict_last). ptxas on sm_100 only
// accepts L2 eviction hints with .v8.b32 / .v4.b64 shapes -> use v4.b64
// (32 bytes = 8 packed 32-bit lanes per load).
struct U64x4 { unsigned long long a, b, c, d; };
__device__ __forceinline__ U64x4 ldg_keep_b64x4(const void* p) {
    U64x4 v;
    asm volatile("ld.global.nc.L2::evict_last.v4.b64 {%0,%1,%2,%3}, [%4];"
                 : "=l"(v.a), "=l"(v.b), "=l"(v.c), "=l"(v.d) : "l"(p));
    return v;
}
__device__ __forceinline__ void unpack_i2(unsigned long long u, int& lo, int& hi) {
    lo = (int)(unsigned)(u & 0xFFFFFFFFull);
    hi = (int)(unsigned)(u >> 32);
}
__device__ __forceinline__ void unpack_f2(unsigned long long u, float& lo, float& hi) {
    lo = __uint_as_float((unsigned)(u & 0xFFFFFFFFull));
    hi = __uint_as_float((unsigned)(u >> 32));
}

// ---------------------------------------------------------------------------
// K0: softmax over the 4 alphas (single thread — trivial)
// ---------------------------------------------------------------------------
__global__ void softmax_alpha_kernel(const float* __restrict__ alpha) {
    float m = alpha[0];
    #pragma unroll
    for (int i = 1; i < NUM_LAYERS + 1; i++) m = fmaxf(m, alpha[i]);
    float s = 0.f;
    float e[NUM_LAYERS + 1];
    #pragma unroll
    for (int i = 0; i < NUM_LAYERS + 1; i++) { e[i] = expf(alpha[i] - m); s += e[i]; }
    float inv = 1.f / s;
    #pragma unroll
    for (int i = 0; i < NUM_LAYERS + 1; i++) d_a[i] = e[i] * inv;
}

// ---------------------------------------------------------------------------
// K1: y[n] = embedding[node_indices[n]] @ W    (one warp per node)
//     Also zeroes the three propagation buffers.
// ---------------------------------------------------------------------------
__global__ void __launch_bounds__(256)
gemv_kernel(const int*   __restrict__ node_indices,
            const float* __restrict__ embedding,
            const float* __restrict__ W) {
    __shared__ float sW0[EMBED_DIM];
    __shared__ float sW1[EMBED_DIM];
    int t = threadIdx.x;
    if (t < EMBED_DIM) {
        sW0[t] = W[2 * t + 0];
        sW1[t] = W[2 * t + 1];
    }
    __syncthreads();

    int gtid = blockIdx.x * blockDim.x + threadIdx.x;

    // Zero prop buffers (grid comfortably covers NUM_NODES)
    if (gtid < NUM_NODES) {
        float2 z = make_float2(0.f, 0.f);
        d_p1[gtid] = z; d_p2[gtid] = z; d_p3[gtid] = z;
    }

    int warp = gtid >> 5;
    int lane = gtid & 31;
    if (warp >= NUM_NODES) return;

    int nid = node_indices[warp];
    const float4* erow = reinterpret_cast<const float4*>(embedding + (size_t)nid * EMBED_DIM);
    float4 e = __ldg(erow + lane);                      // 128B coalesced per warp
    const float4* w0 = reinterpret_cast<const float4*>(sW0);
    const float4* w1 = reinterpret_cast<const float4*>(sW1);
    float4 a0 = w0[lane];
    float4 a1 = w1[lane];

    float s0 = e.x * a0.x + e.y * a0.y + e.z * a0.z + e.w * a0.w;
    float s1 = e.x * a1.x + e.y * a1.y + e.z * a1.z + e.w * a1.w;

    #pragma unroll
    for (int off = 16; off > 0; off >>= 1) {
        s0 += __shfl_xor_sync(0xFFFFFFFFu, s0, off);
        s1 += __shfl_xor_sync(0xFFFFFFFFu, s1, off);
    }
    if (lane == 0) d_y[warp] = make_float2(s0, s1);
}

// ---------------------------------------------------------------------------
// K2..K4: SpMM in D=2. Each thread handles 8 edges:
//   - 3 x 256-bit evict_last loads (rows, cols, vals) = 0.375 loads/edge,
//     pinning the 19.2MB edge stream in L2 for reuse across layers/replays
//   - 8 independent float2 gathers batched for deep MLP
//   - one red.global.add.v2.f32 per edge
// NUM_EDGES = 1.6M divisible by 8; 32B loads are 32B-aligned.
// ---------------------------------------------------------------------------
__global__ void __launch_bounds__(256)
spmm_kernel(const int*   __restrict__ adj_row,
            const int*   __restrict__ adj_col,
            const float* __restrict__ adj_val,
            const float2* __restrict__ cur,
            float2*       __restrict__ nxt) {
    const int noct = NUM_EDGES / EDGES_PER_THREAD;     // 200,000 octs
    int o = blockIdx.x * blockDim.x + threadIdx.x;
    if (o >= noct) return;

    U64x4 rr = ldg_keep_b64x4(reinterpret_cast<const char*>(adj_row) + 32ull * o);
    U64x4 cc = ldg_keep_b64x4(reinterpret_cast<const char*>(adj_col) + 32ull * o);
    U64x4 vv = ldg_keep_b64x4(reinterpret_cast<const char*>(adj_val) + 32ull * o);

    int r0, r1, r2, r3, r4, r5, r6, r7;
    unpack_i2(rr.a, r0, r1); unpack_i2(rr.b, r2, r3);
    unpack_i2(rr.c, r4, r5); unpack_i2(rr.d, r6, r7);
    int c0, c1, c2, c3, c4, c5, c6, c7;
    unpack_i2(cc.a, c0, c1); unpack_i2(cc.b, c2, c3);
    unpack_i2(cc.c, c4, c5); unpack_i2(cc.d, c6, c7);
    float v0, v1, v2, v3, v4, v5, v6, v7;
    unpack_f2(vv.a, v0, v1); unpack_f2(vv.b, v2, v3);
    unpack_f2(vv.c, v4, v5); unpack_f2(vv.d, v6, v7);

    // Batch all 8 random gathers (independent -> overlapped in flight)
    float2 x0 = __ldg(&cur[c0]);
    float2 x1 = __ldg(&cur[c1]);
    float2 x2 = __ldg(&cur[c2]);
    float2 x3 = __ldg(&cur[c3]);
    float2 x4 = __ldg(&cur[c4]);
    float2 x5 = __ldg(&cur[c5]);
    float2 x6 = __ldg(&cur[c6]);
    float2 x7 = __ldg(&cur[c7]);

    red_add_f2(&nxt[r0], v0 * x0.x, v0 * x0.y);
    red_add_f2(&nxt[r1], v1 * x1.x, v1 * x1.y);
    red_add_f2(&nxt[r2], v2 * x2.x, v2 * x2.y);
    red_add_f2(&nxt[r3], v3 * x3.x, v3 * x3.y);
    red_add_f2(&nxt[r4], v4 * x4.x, v4 * x4.y);
    red_add_f2(&nxt[r5], v5 * x5.x, v5 * x5.y);
    red_add_f2(&nxt[r6], v6 * x6.x, v6 * x6.y);
    red_add_f2(&nxt[r7], v7 * x7.x, v7 * x7.y);
}

// ---------------------------------------------------------------------------
// K5: out[n] = a0*y + a1*p1 + a2*p2 + a3*p3 + b
// ---------------------------------------------------------------------------
__global__ void __launch_bounds__(256)
combine_kernel(const float* __restrict__ b, float2* __restrict__ out) {
    int n = blockIdx.x * blockDim.x + threadIdx.x;
    if (n >= NUM_NODES) return;
    float a0 = d_a[0], a1 = d_a[1], a2 = d_a[2], a3 = d_a[3];
    float2 y  = d_y[n];
    float2 p1 = d_p1[n];
    float2 p2 = d_p2[n];
    float2 p3 = d_p3[n];
    float2 o;
    o.x = a0 * y.x + a1 * p1.x + a2 * p2.x + a3 * p3.x + b[0];
    o.y = a0 * y.y + a1 * p1.y + a2 * p2.y + a3 * p3.y + b[1];
    out[n] = o;
}

// ---------------------------------------------------------------------------
// Launch: inputs per metadata order:
// 0 node_indices(int32) 1 adj_row(int32) 2 adj_col(int32) 3 adj_val(f32)
// 4 embedding(f32) 5 alpha(f32) 6 W(f32) 7 b(f32)
// ---------------------------------------------------------------------------
extern "C" void kernel_launch(void* const* d_in, const int* in_sizes, int n_in,
                              void* d_out, int out_size) {
    const int*   node_indices = (const int*)  d_in[0];
    const int*   adj_row      = (const int*)  d_in[1];
    const int*   adj_col      = (const int*)  d_in[2];
    const float* adj_val      = (const float*)d_in[3];
    const float* embedding    = (const float*)d_in[4];
    const float* alpha        = (const float*)d_in[5];
    const float* W            = (const float*)d_in[6];
    const float* b            = (const float*)d_in[7];
    float2* out = (float2*)d_out;

    float2 *p_y, *p_p1, *p_p2, *p_p3;
    cudaGetSymbolAddress((void**)&p_y,  d_y);
    cudaGetSymbolAddress((void**)&p_p1, d_p1);
    cudaGetSymbolAddress((void**)&p_p2, d_p2);
    cudaGetSymbolAddress((void**)&p_p3, d_p3);

    softmax_alpha_kernel<<<1, 1>>>(alpha);

    int gemv_blocks = (NUM_NODES + 7) / 8;     // one warp per node
    gemv_kernel<<<gemv_blocks, 256>>>(node_indices, embedding, W);

    int octs = NUM_EDGES / EDGES_PER_THREAD;   // 200,000
    int spmm_blocks = (octs + 255) / 256;
    spmm_kernel<<<spmm_blocks, 256>>>(adj_row, adj_col, adj_val, p_y,  p_p1);
    spmm_kernel<<<spmm_blocks, 256>>>(adj_row, adj_col, adj_val, p_p1, p_p2);
    spmm_kernel<<<spmm_blocks, 256>>>(adj_row, adj_col, adj_val, p_p2, p_p3);

    int comb_blocks = (NUM_NODES + 255) / 256;
    combine_kernel<<<comb_blocks, 256>>>(b, out);
}

// round 8
// speedup vs baseline: 1.0163x; 1.0163x over previous
#include <cuda_runtime.h>
#include <cuda_bf16.h>
#include <math.h>

// Problem constants (fixed by the reference)
#define NUM_NODES   100000
#define NUM_EDGES   1600000
#define EMBED_DIM   128
#define NUM_CLASSES 2
#define NUM_LAYERS  3

#define SPMM_BLOCK  512

// Scratch: __device__ globals (no allocations allowed).
__device__ float2 d_y [NUM_NODES];   // y = emb[idx] @ W
__device__ float2 d_p1[NUM_NODES];   // A y
__device__ float2 d_p2[NUM_NODES];   // A^2 y
__device__ float2 d_p3[NUM_NODES];   // A^3 y

// Software grid barrier state (persistent across graph replays: the
// count-reset + generation-bump pattern is self-restoring).
__device__ unsigned int g_bar_count = 0;
__device__ volatile unsigned int g_bar_gen = 0;

// One 64-bit vector reduction per edge (no return -> REDG fast path in L2).
__device__ __forceinline__ void red_add_f2(float2* addr, float vx, float vy) {
    asm volatile("red.global.add.v2.f32 [%0], {%1, %2};"
                 :: "l"(addr), "f"(vx), "f"(vy) : "memory");
}

// Gather load: L2-only (.cg) so random gather traffic does NOT allocate in L1,
// preserving L1 residency of the per-SM edge-stream chunk across layers.
__device__ __forceinline__ float2 ldcg_f2(const float2* p) {
    float2 v;
    asm volatile("ld.global.cg.v2.f32 {%0, %1}, [%2];"
                 : "=f"(v.x), "=f"(v.y) : "l"(p));
    return v;
}

// ---------------------------------------------------------------------------
// K1: y[n] = embedding[node_indices[n]] @ W    (one warp per node)
//     Also zeroes the three propagation buffers.
// ---------------------------------------------------------------------------
__global__ void __launch_bounds__(256)
gemv_kernel(const int*   __restrict__ node_indices,
            const float* __restrict__ embedding,
            const float* __restrict__ W) {
    __shared__ float sW0[EMBED_DIM];
    __shared__ float sW1[EMBED_DIM];
    int t = threadIdx.x;
    if (t < EMBED_DIM) {
        sW0[t] = W[2 * t + 0];
        sW1[t] = W[2 * t + 1];
    }
    __syncthreads();

    int gtid = blockIdx.x * blockDim.x + threadIdx.x;

    // Zero prop buffers (grid comfortably covers NUM_NODES)
    if (gtid < NUM_NODES) {
        float2 z = make_float2(0.f, 0.f);
        d_p1[gtid] = z; d_p2[gtid] = z; d_p3[gtid] = z;
    }

    int warp = gtid >> 5;
    int lane = gtid & 31;
    if (warp >= NUM_NODES) return;

    int nid = node_indices[warp];
    const float4* erow = reinterpret_cast<const float4*>(embedding + (size_t)nid * EMBED_DIM);
    float4 e = __ldg(erow + lane);                      // 128B coalesced per warp
    const float4* w0 = reinterpret_cast<const float4*>(sW0);
    const float4* w1 = reinterpret_cast<const float4*>(sW1);
    float4 a0 = w0[lane];
    float4 a1 = w1[lane];

    float s0 = e.x * a0.x + e.y * a0.y + e.z * a0.z + e.w * a0.w;
    float s1 = e.x * a1.x + e.y * a1.y + e.z * a1.z + e.w * a1.w;

    #pragma unroll
    for (int off = 16; off > 0; off >>= 1) {
        s0 += __shfl_xor_sync(0xFFFFFFFFu, s0, off);
        s1 += __shfl_xor_sync(0xFFFFFFFFu, s1, off);
    }
    if (lane == 0) d_y[warp] = make_float2(s0, s1);
}

// ---------------------------------------------------------------------------
// Grid barrier: all co-resident blocks arrive (thread 0), last one resets the
// count and bumps the generation; others spin with nanosleep backoff.
// ---------------------------------------------------------------------------
__device__ __forceinline__ void grid_barrier() {
    __syncthreads();
    if (threadIdx.x == 0) {
        __threadfence();                       // make this block's REDs visible
        unsigned gen = g_bar_gen;
        unsigned arrived = atomicAdd(&g_bar_count, 1u);
        if (arrived == gridDim.x - 1u) {
            g_bar_count = 0;                   // safe: everyone has arrived
            __threadfence();
            g_bar_gen = gen + 1u;              // release
        } else {
            while (g_bar_gen == gen) { __nanosleep(64); }
        }
        __threadfence();                       // acquire
    }
    __syncthreads();
}

// ---------------------------------------------------------------------------
// K2: fused 3-layer SpMM, persistent blocks + software grid barrier.
// Each thread processes 4 edges per grid-stride iteration:
//   - int4/float4 edge loads via __ldg: allocate in L1; the SAME block reads
//     the SAME quads each layer -> L1 hits in layers 2-3 (L1 persists within
//     a kernel; ~130KB edge chunk per SM fits in 228KB L1)
//   - gathers via ld.global.cg (L2-only, keeps L1 for edges)
//   - one red.global.add.v2.f32 per edge
// ---------------------------------------------------------------------------
__global__ void __launch_bounds__(SPMM_BLOCK)
spmm3_kernel(const int*   __restrict__ adj_row,
             const int*   __restrict__ adj_col,
             const float* __restrict__ adj_val) {
    const int nquad  = NUM_EDGES / 4;                  // 400,000
    const int stride = gridDim.x * blockDim.x;
    const int tid0   = blockIdx.x * blockDim.x + threadIdx.x;

    const int4*   row4 = reinterpret_cast<const int4*>(adj_row);
    const int4*   col4 = reinterpret_cast<const int4*>(adj_col);
    const float4* val4 = reinterpret_cast<const float4*>(adj_val);

    #pragma unroll 1
    for (int layer = 0; layer < NUM_LAYERS; layer++) {
        const float2* cur = (layer == 0) ? d_y  : (layer == 1) ? d_p1 : d_p2;
        float2*       nxt = (layer == 0) ? d_p1 : (layer == 1) ? d_p2 : d_p3;

        for (int q = tid0; q < nquad; q += stride) {
            int4   r4 = __ldg(row4 + q);
            int4   c4 = __ldg(col4 + q);
            float4 v4 = __ldg(val4 + q);

            float2 x0 = ldcg_f2(&cur[c4.x]);
            float2 x1 = ldcg_f2(&cur[c4.y]);
            float2 x2 = ldcg_f2(&cur[c4.z]);
            float2 x3 = ldcg_f2(&cur[c4.w]);

            red_add_f2(&nxt[r4.x], v4.x * x0.x, v4.x * x0.y);
            red_add_f2(&nxt[r4.y], v4.y * x1.x, v4.y * x1.y);
            red_add_f2(&nxt[r4.z], v4.z * x2.x, v4.z * x2.y);
            red_add_f2(&nxt[r4.w], v4.w * x3.x, v4.w * x3.y);
        }

        if (layer < NUM_LAYERS - 1) grid_barrier();
    }
}

// ---------------------------------------------------------------------------
// K3: out[n] = a0*y + a1*p1 + a2*p2 + a3*p3 + b   (softmax folded in)
// ---------------------------------------------------------------------------
__global__ void __launch_bounds__(256)
combine_kernel(const float* __restrict__ alpha,
               const float* __restrict__ b,
               float2* __restrict__ out) {
    int n = blockIdx.x * blockDim.x + threadIdx.x;
    if (n >= NUM_NODES) return;

    float al0 = __ldg(&alpha[0]), al1 = __ldg(&alpha[1]);
    float al2 = __ldg(&alpha[2]), al3 = __ldg(&alpha[3]);
    float m = fmaxf(fmaxf(al0, al1), fmaxf(al2, al3));
    float e0 = expf(al0 - m), e1 = expf(al1 - m);
    float e2 = expf(al2 - m), e3 = expf(al3 - m);
    float inv = 1.f / (e0 + e1 + e2 + e3);
    float a0 = e0 * inv, a1 = e1 * inv, a2 = e2 * inv, a3 = e3 * inv;

    float2 y  = d_y[n];
    float2 p1 = d_p1[n];
    float2 p2 = d_p2[n];
    float2 p3 = d_p3[n];
    float2 o;
    o.x = a0 * y.x + a1 * p1.x + a2 * p2.x + a3 * p3.x + __ldg(&b[0]);
    o.y = a0 * y.y + a1 * p1.y + a2 * p2.y + a3 * p3.y + __ldg(&b[1]);
    out[n] = o;
}

// ---------------------------------------------------------------------------
// Launch: inputs per metadata order:
// 0 node_indices(int32) 1 adj_row(int32) 2 adj_col(int32) 3 adj_val(f32)
// 4 embedding(f32) 5 alpha(f32) 6 W(f32) 7 b(f32)
// ---------------------------------------------------------------------------
extern "C" void kernel_launch(void* const* d_in, const int* in_sizes, int n_in,
                              void* d_out, int out_size) {
    const int*   node_indices = (const int*)  d_in[0];
    const int*   adj_row      = (const int*)  d_in[1];
    const int*   adj_col      = (const int*)  d_in[2];
    const float* adj_val      = (const float*)d_in[3];
    const float* embedding    = (const float*)d_in[4];
    const float* alpha        = (const float*)d_in[5];
    const float* W            = (const float*)d_in[6];
    const float* b            = (const float*)d_in[7];
    float2* out = (float2*)d_out;

    // Persistent grid sized for guaranteed co-residency (software barrier).
    int dev = 0, sms = 0, maxb = 0;
    cudaGetDevice(&dev);
    cudaDeviceGetAttribute(&sms, cudaDevAttrMultiProcessorCount, dev);
    cudaOccupancyMaxActiveBlocksPerMultiprocessor(&maxb, spmm3_kernel, SPMM_BLOCK, 0);
    if (maxb < 1) maxb = 1;
    int spmm_grid = sms * maxb;
    // Don't exceed the task count by an absurd margin (still must all arrive
    // at the barrier, which they do regardless of work).
    int max_useful = (NUM_EDGES / 4 + SPMM_BLOCK - 1) / SPMM_BLOCK;
    if (spmm_grid > max_useful) spmm_grid = max_useful;

    int gemv_blocks = (NUM_NODES + 7) / 8;     // one warp per node
    gemv_kernel<<<gemv_blocks, 256>>>(node_indices, embedding, W);

    spmm3_kernel<<<spmm_grid, SPMM_BLOCK>>>(adj_row, adj_col, adj_val);

    int comb_blocks = (NUM_NODES + 255) / 256;
    combine_kernel<<<comb_blocks, 256>>>(alpha, b, out);
}